// round 3
// baseline (speedup 1.0000x reference)
#include <cuda_runtime.h>
#include <math.h>

// Problem shape (fixed by the reference): qkv [B, S, 3, H, D] fp32 -> out [B, S, H, D] fp32
#define B_SZ   2
#define SEQ    2048
#define NH     16
#define DH     64

// Tiling
#define BM     64      // query rows per block
#define BN     64      // kv rows per tile
#define NWARP  4       // each warp owns 16 query rows

// Shared-memory strides (floats), chosen for conflict-free B-fragment access:
//  K/P fragment pattern addr = g*stride + t (+consts), stride%32 == 4 -> banks 4g+t all distinct
//  V fragment pattern addr = t*stride + g (+consts), stride%32 == 8 -> banks 8t+g all distinct
#define KST    68
#define VST    72
#define PST    68

__device__ __forceinline__ unsigned f2tf32(float x) {
    unsigned r;
    asm("cvt.rna.tf32.f32 %0, %1;" : "=r"(r) : "f"(x));
    return r;
}

__device__ __forceinline__ void mma_tf32(float c[4], const unsigned a[4],
                                         unsigned b0, unsigned b1) {
    asm volatile(
        "mma.sync.aligned.m16n8k8.row.col.f32.tf32.tf32.f32 "
        "{%0,%1,%2,%3}, {%4,%5,%6,%7}, {%8,%9}, {%0,%1,%2,%3};"
        : "+f"(c[0]), "+f"(c[1]), "+f"(c[2]), "+f"(c[3])
        : "r"(a[0]), "r"(a[1]), "r"(a[2]), "r"(a[3]), "r"(b0), "r"(b1));
}

__global__ void __launch_bounds__(128)
fa_fwd_kernel(const float* __restrict__ qkv, float* __restrict__ out)
{
    extern __shared__ float smem[];
    float* Ks = smem;                    // [BN][KST]  (tf32-rounded K tile, row=key, col=d)
    float* Vs = Ks + BN * KST;           // [BN][VST]  (tf32-rounded V tile, row=key, col=d)
    float* Ps = Vs + BN * VST;           // [NWARP][16][PST] per-warp P staging

    const int tid  = threadIdx.x;
    const int warp = tid >> 5;
    const int lane = tid & 31;
    const int g    = lane >> 2;          // groupID (row within fragment)
    const int t    = lane & 3;           // threadID_in_group

    const int mtile = blockIdx.x;
    const int b     = blockIdx.y / NH;
    const int h     = blockIdx.y % NH;
    const int m0    = mtile * BM;

    const int rowstr = 3 * NH * DH;      // seq-position stride in qkv (3072 floats)

    const float* qbase = qkv + (size_t)b * SEQ * rowstr + h * DH;       // slot 0
    const float* kbase = qbase + NH * DH;                               // slot 1

    // fold softmax scale and log2(e) into Q so softmax uses exp2
    const float qs = 0.125f * 1.4426950408889634f;   // (1/sqrt(64)) * log2e

    // ---- load this warp's Q rows (m0 + warp*16 + {g, g+8}) as tf32 A-fragments ----
    unsigned qf[8][4];
    {
        const float* q0 = qbase + (size_t)(m0 + warp * 16 + g) * rowstr;
        const float* q1 = q0 + (size_t)8 * rowstr;
#pragma unroll
        for (int ks = 0; ks < 8; ks++) {
            int c = ks * 8 + t;
            qf[ks][0] = f2tf32(q0[c]     * qs);
            qf[ks][1] = f2tf32(q1[c]     * qs);
            qf[ks][2] = f2tf32(q0[c + 4] * qs);
            qf[ks][3] = f2tf32(q1[c + 4] * qs);
        }
    }

    float mr0 = -INFINITY, mr1 = -INFINITY;   // running row max (log2 domain)
    float l0 = 0.f, l1 = 0.f;                 // running row sum
    float oacc[8][4];
#pragma unroll
    for (int nf = 0; nf < 8; nf++) {
        oacc[nf][0] = 0.f; oacc[nf][1] = 0.f; oacc[nf][2] = 0.f; oacc[nf][3] = 0.f;
    }

    float* Pw = Ps + warp * 16 * PST;

    for (int it = 0; it <= mtile; it++) {
        const int n0 = it * BN;
        __syncthreads();   // all warps done reading previous K/V tiles

        // ---- cooperative K/V tile load (64x64 fp32 each), round to tf32 in smem ----
#pragma unroll
        for (int i = 0; i < 8; i++) {
            int idx = tid + i * 128;              // 0..1023 float4s
            int row = idx >> 4;
            int c4  = (idx & 15) << 2;
            const float* gk = kbase + (size_t)(n0 + row) * rowstr + c4;
            float4 k4 = *(const float4*)gk;
            float4 v4 = *(const float4*)(gk + NH * DH);
            float* kd = Ks + row * KST + c4;
            kd[0] = __uint_as_float(f2tf32(k4.x));
            kd[1] = __uint_as_float(f2tf32(k4.y));
            kd[2] = __uint_as_float(f2tf32(k4.z));
            kd[3] = __uint_as_float(f2tf32(k4.w));
            float* vd = Vs + row * VST + c4;
            vd[0] = __uint_as_float(f2tf32(v4.x));
            vd[1] = __uint_as_float(f2tf32(v4.y));
            vd[2] = __uint_as_float(f2tf32(v4.z));
            vd[3] = __uint_as_float(f2tf32(v4.w));
        }
        __syncthreads();

        // ---- S = (Q*scale) @ K^T : 8 n-frags x 8 k-steps of m16n8k8 ----
        float sacc[8][4];
#pragma unroll
        for (int nf = 0; nf < 8; nf++) {
            sacc[nf][0] = 0.f; sacc[nf][1] = 0.f; sacc[nf][2] = 0.f; sacc[nf][3] = 0.f;
        }
#pragma unroll
        for (int ks = 0; ks < 8; ks++) {
#pragma unroll
            for (int nf = 0; nf < 8; nf++) {
                const float* kp = Ks + (nf * 8 + g) * KST + ks * 8 + t;
                unsigned b0 = __float_as_uint(kp[0]);
                unsigned b1 = __float_as_uint(kp[4]);
                mma_tf32(sacc[nf], qf[ks], b0, b1);
            }
        }

        // ---- causal mask on the diagonal tile ----
        if (it == mtile) {
            const int rl0 = warp * 16 + g;
            const int rl1 = rl0 + 8;
#pragma unroll
            for (int nf = 0; nf < 8; nf++) {
                int c0 = nf * 8 + 2 * t;
                int c1 = c0 + 1;
                if (c0 > rl0) sacc[nf][0] = -1e30f;
                if (c1 > rl0) sacc[nf][1] = -1e30f;
                if (c0 > rl1) sacc[nf][2] = -1e30f;
                if (c1 > rl1) sacc[nf][3] = -1e30f;
            }
        }

        // ---- online softmax (base-2) ----
        float rmax0 = -INFINITY, rmax1 = -INFINITY;
#pragma unroll
        for (int nf = 0; nf < 8; nf++) {
            rmax0 = fmaxf(rmax0, fmaxf(sacc[nf][0], sacc[nf][1]));
            rmax1 = fmaxf(rmax1, fmaxf(sacc[nf][2], sacc[nf][3]));
        }
        rmax0 = fmaxf(rmax0, __shfl_xor_sync(0xffffffffu, rmax0, 1));
        rmax0 = fmaxf(rmax0, __shfl_xor_sync(0xffffffffu, rmax0, 2));
        rmax1 = fmaxf(rmax1, __shfl_xor_sync(0xffffffffu, rmax1, 1));
        rmax1 = fmaxf(rmax1, __shfl_xor_sync(0xffffffffu, rmax1, 2));

        float mn0 = fmaxf(mr0, rmax0);
        float mn1 = fmaxf(mr1, rmax1);
        float alpha0 = exp2f(mr0 - mn0);
        float alpha1 = exp2f(mr1 - mn1);
        mr0 = mn0; mr1 = mn1;
        l0 *= alpha0; l1 *= alpha1;
#pragma unroll
        for (int nf = 0; nf < 8; nf++) {
            oacc[nf][0] *= alpha0; oacc[nf][1] *= alpha0;
            oacc[nf][2] *= alpha1; oacc[nf][3] *= alpha1;
        }

        float rs0 = 0.f, rs1 = 0.f;
#pragma unroll
        for (int nf = 0; nf < 8; nf++) {
            float p00 = exp2f(sacc[nf][0] - mn0);
            float p01 = exp2f(sacc[nf][1] - mn0);
            float p10 = exp2f(sacc[nf][2] - mn1);
            float p11 = exp2f(sacc[nf][3] - mn1);
            // round P to tf32 once; sum the SAME rounded values for l (consistency)
            p00 = __uint_as_float(f2tf32(p00));
            p01 = __uint_as_float(f2tf32(p01));
            p10 = __uint_as_float(f2tf32(p10));
            p11 = __uint_as_float(f2tf32(p11));
            rs0 += p00 + p01;
            rs1 += p10 + p11;
            int c = nf * 8 + 2 * t;
            *(float2*)(Pw + g * PST + c)       = make_float2(p00, p01);
            *(float2*)(Pw + (g + 8) * PST + c) = make_float2(p10, p11);
        }
        rs0 += __shfl_xor_sync(0xffffffffu, rs0, 1);
        rs0 += __shfl_xor_sync(0xffffffffu, rs0, 2);
        rs1 += __shfl_xor_sync(0xffffffffu, rs1, 1);
        rs1 += __shfl_xor_sync(0xffffffffu, rs1, 2);
        l0 += rs0; l1 += rs1;

        __syncwarp();   // P staged by this warp, consumed cross-lane below

        // ---- O += P @ V ----
#pragma unroll
        for (int ks = 0; ks < 8; ks++) {
            unsigned a[4];
            a[0] = __float_as_uint(Pw[g * PST + ks * 8 + t]);
            a[1] = __float_as_uint(Pw[(g + 8) * PST + ks * 8 + t]);
            a[2] = __float_as_uint(Pw[g * PST + ks * 8 + t + 4]);
            a[3] = __float_as_uint(Pw[(g + 8) * PST + ks * 8 + t + 4]);
#pragma unroll
            for (int nf = 0; nf < 8; nf++) {
                const float* vp = Vs + (ks * 8 + t) * VST + nf * 8 + g;
                unsigned b0 = __float_as_uint(vp[0]);
                unsigned b1 = __float_as_uint(vp[4 * VST]);
                mma_tf32(oacc[nf], a, b0, b1);
            }
        }
    }

    // ---- epilogue: normalize and store ----
    const float inv0 = 1.0f / l0;
    const float inv1 = 1.0f / l1;
    const int r0 = m0 + warp * 16 + g;
    float* o0 = out + ((size_t)(b * SEQ + r0) * NH + h) * DH;
    float* o1 = o0 + (size_t)8 * NH * DH;
#pragma unroll
    for (int nf = 0; nf < 8; nf++) {
        int c = nf * 8 + 2 * t;
        *(float2*)(o0 + c) = make_float2(oacc[nf][0] * inv0, oacc[nf][1] * inv0);
        *(float2*)(o1 + c) = make_float2(oacc[nf][2] * inv1, oacc[nf][3] * inv1);
    }
}

extern "C" void kernel_launch(void* const* d_in, const int* in_sizes, int n_in,
                              void* d_out, int out_size)
{
    (void)in_sizes; (void)n_in; (void)out_size;
    const float* qkv = (const float*)d_in[0];
    float* out = (float*)d_out;

    const int smem_bytes = (BN * KST + BN * VST + NWARP * 16 * PST) * (int)sizeof(float);
    // > 48KB dynamic smem needs opt-in; idempotent, capture-safe (not a stream op)
    cudaFuncSetAttribute(fa_fwd_kernel, cudaFuncAttributeMaxDynamicSharedMemorySize, smem_bytes);

    dim3 grid(SEQ / BM, B_SZ * NH);
    fa_fwd_kernel<<<grid, 128, smem_bytes>>>(qkv, out);
}

// round 6
// speedup vs baseline: 1.1285x; 1.1285x over previous
#include <cuda_runtime.h>
#include <math.h>

// qkv [B, S, 3, H, D] fp32 -> out [B, S, H, D] fp32
#define B_SZ   2
#define SEQ    2048
#define NH     16
#define DH     64

#define BM     64      // query rows per block
#define BN     64      // kv rows per tile
#define NWARP  4

// Shared strides (floats), conflict-free for fragment reads:
//  K pattern addr = g*KST + t  : KST%32==4 -> banks 4g+t distinct
//  V pattern addr = t*VST + g  : VST%32==8 -> banks 8t+g distinct
#define KST    68
#define VST    72

__device__ __forceinline__ unsigned f2tf32(float x) {
    unsigned r;
    asm("cvt.rna.tf32.f32 %0, %1;" : "=r"(r) : "f"(x));
    return r;
}

__device__ __forceinline__ void mma_tf32(float c[4], const unsigned a[4],
                                         unsigned b0, unsigned b1) {
    asm volatile(
        "mma.sync.aligned.m16n8k8.row.col.f32.tf32.tf32.f32 "
        "{%0,%1,%2,%3}, {%4,%5,%6,%7}, {%8,%9}, {%0,%1,%2,%3};"
        : "+f"(c[0]), "+f"(c[1]), "+f"(c[2]), "+f"(c[3])
        : "r"(a[0]), "r"(a[1]), "r"(a[2]), "r"(a[3]), "r"(b0), "r"(b1));
}

__device__ __forceinline__ void cpasync16(unsigned saddr, const void* gaddr) {
    asm volatile("cp.async.cg.shared.global [%0], [%1], 16;" :: "r"(saddr), "l"(gaddr));
}
__device__ __forceinline__ void cpasync_commit() {
    asm volatile("cp.async.commit_group;");
}
__device__ __forceinline__ void cpasync_wait0() {
    asm volatile("cp.async.wait_group 0;");
}

__global__ void __launch_bounds__(128)
fa_fwd_kernel(const float* __restrict__ qkv, float* __restrict__ out)
{
    extern __shared__ float smem[];
    // layout: K0 | K1 | V0 | V1
    float* Ksm = smem;                       // [2][BN][KST]
    float* Vsm = smem + 2 * BN * KST;        // [2][BN][VST]

    const int tid  = threadIdx.x;
    const int warp = tid >> 5;
    const int lane = tid & 31;
    const int g    = lane >> 2;
    const int t    = lane & 3;

    // shuffle sources for P relayout (C-frag -> A-frag), quad-local
    const int srcA = (lane & ~3) | (t >> 1);
    const int srcB = srcA + 2;
    const bool odd = (t & 1);

    const int mtile = blockIdx.x;
    const int b     = blockIdx.y / NH;
    const int h     = blockIdx.y % NH;
    const int m0    = mtile * BM;

    const int rowstr = 3 * NH * DH;          // 3072 floats per seq position

    const float* qbase = qkv + (size_t)b * SEQ * rowstr + h * DH;   // slot 0
    const float* kbase = qbase + NH * DH;                           // slot 1 (V at +NH*DH more)

    const float qs = 0.125f * 1.4426950408889634f;  // (1/sqrt(64)) * log2e

    // per-thread loader coords (16 float4s per thread per tile)
    // idx = tid + i*128 ; row = idx>>4 ; c4 = (idx&15)<<2
    unsigned kdst[8], vdst[8];
    const float* gsrc[8];
    {
        unsigned ksh = (unsigned)__cvta_generic_to_shared(Ksm);
        unsigned vsh = (unsigned)__cvta_generic_to_shared(Vsm);
#pragma unroll
        for (int i = 0; i < 8; i++) {
            int idx = tid + i * 128;
            int row = idx >> 4;
            int c4  = (idx & 15) << 2;
            kdst[i] = ksh + (unsigned)(row * KST + c4) * 4u;
            vdst[i] = vsh + (unsigned)(row * VST + c4) * 4u;
            gsrc[i] = kbase + (size_t)row * rowstr + c4;
        }
    }
    const unsigned kbufB = (unsigned)(BN * KST) * 4u;   // byte offset buffer 1
    const unsigned vbufB = (unsigned)(BN * VST) * 4u;

    // ---- prologue: issue tile 0 into buffer 0 ----
#pragma unroll
    for (int i = 0; i < 8; i++) {
        const float* gk = gsrc[i];                  // n0 = 0
        cpasync16(kdst[i], gk);
        cpasync16(vdst[i], gk + NH * DH);
    }
    cpasync_commit();

    // ---- load this warp's Q rows as tf32 A-fragments (overlaps the cp.async) ----
    unsigned qf[8][4];
    {
        const float* q0 = qbase + (size_t)(m0 + warp * 16 + g) * rowstr;
        const float* q1 = q0 + (size_t)8 * rowstr;
#pragma unroll
        for (int ks = 0; ks < 8; ks++) {
            int c = ks * 8 + t;
            qf[ks][0] = f2tf32(q0[c]     * qs);
            qf[ks][1] = f2tf32(q1[c]     * qs);
            qf[ks][2] = f2tf32(q0[c + 4] * qs);
            qf[ks][3] = f2tf32(q1[c + 4] * qs);
        }
    }

    float mr0 = -INFINITY, mr1 = -INFINITY;
    float l0 = 0.f, l1 = 0.f;
    float oacc[8][4];
#pragma unroll
    for (int nf = 0; nf < 8; nf++) {
        oacc[nf][0] = 0.f; oacc[nf][1] = 0.f; oacc[nf][2] = 0.f; oacc[nf][3] = 0.f;
    }

    for (int it = 0; it <= mtile; it++) {
        const float* Ks = Ksm + (it & 1) * (BN * KST);
        const float* Vs = Vsm + (it & 1) * (BN * VST);

        cpasync_wait0();        // tile it arrived (this thread's copies)
        __syncthreads();        // visible to all; everyone done with the other buffer

        // prefetch tile it+1 into the other buffer, overlapped with compute below
        if (it < mtile) {
            const size_t goff = (size_t)(it + 1) * BN * rowstr;
            const unsigned ob = ((it + 1) & 1) ? 1u : 0u;
#pragma unroll
            for (int i = 0; i < 8; i++) {
                const float* gk = gsrc[i] + goff;
                cpasync16(kdst[i] + ob * kbufB, gk);
                cpasync16(vdst[i] + ob * vbufB, gk + NH * DH);
            }
            cpasync_commit();
        }

        // ---- S = (Q*scale) @ K^T ----
        float sacc[8][4];
#pragma unroll
        for (int nf = 0; nf < 8; nf++) {
            sacc[nf][0] = 0.f; sacc[nf][1] = 0.f; sacc[nf][2] = 0.f; sacc[nf][3] = 0.f;
        }
#pragma unroll
        for (int ks = 0; ks < 8; ks++) {
#pragma unroll
            for (int nf = 0; nf < 8; nf++) {
                const float* kp = Ks + (nf * 8 + g) * KST + ks * 8 + t;
                unsigned b0 = __float_as_uint(kp[0]);
                unsigned b1 = __float_as_uint(kp[4]);
                mma_tf32(sacc[nf], qf[ks], b0, b1);
            }
        }

        // ---- causal mask on diagonal tile ----
        if (it == mtile) {
            const int rl0 = warp * 16 + g;
            const int rl1 = rl0 + 8;
#pragma unroll
            for (int nf = 0; nf < 8; nf++) {
                int c0 = nf * 8 + 2 * t;
                int c1 = c0 + 1;
                if (c0 > rl0) sacc[nf][0] = -1e30f;
                if (c1 > rl0) sacc[nf][1] = -1e30f;
                if (c0 > rl1) sacc[nf][2] = -1e30f;
                if (c1 > rl1) sacc[nf][3] = -1e30f;
            }
        }

        // ---- online softmax (base-2) ----
        float rmax0 = -INFINITY, rmax1 = -INFINITY;
#pragma unroll
        for (int nf = 0; nf < 8; nf++) {
            rmax0 = fmaxf(rmax0, fmaxf(sacc[nf][0], sacc[nf][1]));
            rmax1 = fmaxf(rmax1, fmaxf(sacc[nf][2], sacc[nf][3]));
        }
        rmax0 = fmaxf(rmax0, __shfl_xor_sync(0xffffffffu, rmax0, 1));
        rmax0 = fmaxf(rmax0, __shfl_xor_sync(0xffffffffu, rmax0, 2));
        rmax1 = fmaxf(rmax1, __shfl_xor_sync(0xffffffffu, rmax1, 1));
        rmax1 = fmaxf(rmax1, __shfl_xor_sync(0xffffffffu, rmax1, 2));

        float mn0 = fmaxf(mr0, rmax0);
        float mn1 = fmaxf(mr1, rmax1);
        float alpha0 = exp2f(mr0 - mn0);
        float alpha1 = exp2f(mr1 - mn1);
        mr0 = mn0; mr1 = mn1;
        l0 *= alpha0; l1 *= alpha1;
#pragma unroll
        for (int nf = 0; nf < 8; nf++) {
            oacc[nf][0] *= alpha0; oacc[nf][1] *= alpha0;
            oacc[nf][2] *= alpha1; oacc[nf][3] *= alpha1;
        }

        float rs0 = 0.f, rs1 = 0.f;
#pragma unroll
        for (int nf = 0; nf < 8; nf++) {
            float p00 = exp2f(sacc[nf][0] - mn0);
            float p01 = exp2f(sacc[nf][1] - mn0);
            float p10 = exp2f(sacc[nf][2] - mn1);
            float p11 = exp2f(sacc[nf][3] - mn1);
            // round P to tf32 once; sum the SAME rounded values for l (consistency)
            p00 = __uint_as_float(f2tf32(p00));
            p01 = __uint_as_float(f2tf32(p01));
            p10 = __uint_as_float(f2tf32(p10));
            p11 = __uint_as_float(f2tf32(p11));
            rs0 += p00 + p01;
            rs1 += p10 + p11;
            sacc[nf][0] = p00; sacc[nf][1] = p01;
            sacc[nf][2] = p10; sacc[nf][3] = p11;
        }
        rs0 += __shfl_xor_sync(0xffffffffu, rs0, 1);
        rs0 += __shfl_xor_sync(0xffffffffu, rs0, 2);
        rs1 += __shfl_xor_sync(0xffffffffu, rs1, 1);
        rs1 += __shfl_xor_sync(0xffffffffu, rs1, 2);
        l0 += rs0; l1 += rs1;

        // ---- O += P @ V  (P relayout C-frag -> A-frag via quad shuffles) ----
#pragma unroll
        for (int ks = 0; ks < 8; ks++) {
            float eA0 = __shfl_sync(0xffffffffu, sacc[ks][0], srcA);
            float oA0 = __shfl_sync(0xffffffffu, sacc[ks][1], srcA);
            float eA1 = __shfl_sync(0xffffffffu, sacc[ks][2], srcA);
            float oA1 = __shfl_sync(0xffffffffu, sacc[ks][3], srcA);
            float eB0 = __shfl_sync(0xffffffffu, sacc[ks][0], srcB);
            float oB0 = __shfl_sync(0xffffffffu, sacc[ks][1], srcB);
            float eB1 = __shfl_sync(0xffffffffu, sacc[ks][2], srcB);
            float oB1 = __shfl_sync(0xffffffffu, sacc[ks][3], srcB);
            unsigned a[4];
            a[0] = __float_as_uint(odd ? oA0 : eA0);
            a[1] = __float_as_uint(odd ? oA1 : eA1);
            a[2] = __float_as_uint(odd ? oB0 : eB0);
            a[3] = __float_as_uint(odd ? oB1 : eB1);
#pragma unroll
            for (int nf = 0; nf < 8; nf++) {
                const float* vp = Vs + (ks * 8 + t) * VST + nf * 8 + g;
                unsigned b0 = __float_as_uint(vp[0]);
                unsigned b1 = __float_as_uint(vp[4 * VST]);
                mma_tf32(oacc[nf], a, b0, b1);
            }
        }
    }

    // ---- epilogue ----
    const float inv0 = 1.0f / l0;
    const float inv1 = 1.0f / l1;
    const int r0 = m0 + warp * 16 + g;
    float* o0 = out + ((size_t)(b * SEQ + r0) * NH + h) * DH;
    float* o1 = o0 + (size_t)8 * NH * DH;
#pragma unroll
    for (int nf = 0; nf < 8; nf++) {
        int c = nf * 8 + 2 * t;
        *(float2*)(o0 + c) = make_float2(oacc[nf][0] * inv0, oacc[nf][1] * inv0);
        *(float2*)(o1 + c) = make_float2(oacc[nf][2] * inv1, oacc[nf][3] * inv1);
    }
}

extern "C" void kernel_launch(void* const* d_in, const int* in_sizes, int n_in,
                              void* d_out, int out_size)
{
    (void)in_sizes; (void)n_in; (void)out_size;
    const float* qkv = (const float*)d_in[0];
    float* out = (float*)d_out;

    const int smem_bytes = 2 * (BN * KST + BN * VST) * (int)sizeof(float);  // 71680 B
    cudaFuncSetAttribute(fa_fwd_kernel, cudaFuncAttributeMaxDynamicSharedMemorySize, smem_bytes);

    dim3 grid(SEQ / BM, B_SZ * NH);
    fa_fwd_kernel<<<grid, 128, smem_bytes>>>(qkv, out);
}

// round 8
// speedup vs baseline: 1.4171x; 1.2558x over previous
#include <cuda_runtime.h>
#include <cstdint>
#include <math.h>

// qkv [B, S, 3, H, D] fp32 -> out [B, S, H, D] fp32
#define B_SZ 2
#define SEQ  2048
#define NH   16
#define DH   64
#define BM   64
#define BN   64

// smem (bytes)
#define KSTG_STRIDE 68              // fp32 staging row stride (words)
#define H_STRIDE    36              // f16 tile row stride (32-bit words): 32 data + 4 pad
#define SM_KSTG 0
#define SM_VSTG (SM_KSTG + 64*KSTG_STRIDE*4)
#define SM_KH   (SM_VSTG + 64*KSTG_STRIDE*4)
#define SM_VH   (SM_KH + 64*H_STRIDE*4)
#define SM_BYTES (SM_VH + 64*H_STRIDE*4)

__device__ __forceinline__ uint32_t packf16(float lo, float hi) {
    uint32_t r;
    asm("cvt.rn.f16x2.f32 %0, %1, %2;" : "=r"(r) : "f"(hi), "f"(lo));
    return r;
}
__device__ __forceinline__ float ex2(float x) {
    float r; asm("ex2.approx.ftz.f32 %0, %1;" : "=f"(r) : "f"(x)); return r;
}
__device__ __forceinline__ void mma_f16(float c[4], const uint32_t a[4],
                                        uint32_t b0, uint32_t b1) {
    asm volatile(
        "mma.sync.aligned.m16n8k16.row.col.f32.f16.f16.f32 "
        "{%0,%1,%2,%3}, {%4,%5,%6,%7}, {%8,%9}, {%0,%1,%2,%3};"
        : "+f"(c[0]), "+f"(c[1]), "+f"(c[2]), "+f"(c[3])
        : "r"(a[0]), "r"(a[1]), "r"(a[2]), "r"(a[3]), "r"(b0), "r"(b1));
}
__device__ __forceinline__ void ldm_x4(uint32_t b[4], uint32_t addr) {
    asm volatile("ldmatrix.sync.aligned.m8n8.x4.shared.b16 {%0,%1,%2,%3}, [%4];"
                 : "=r"(b[0]), "=r"(b[1]), "=r"(b[2]), "=r"(b[3]) : "r"(addr));
}
__device__ __forceinline__ void ldm_x4_t(uint32_t b[4], uint32_t addr) {
    asm volatile("ldmatrix.sync.aligned.m8n8.x4.trans.shared.b16 {%0,%1,%2,%3}, [%4];"
                 : "=r"(b[0]), "=r"(b[1]), "=r"(b[2]), "=r"(b[3]) : "r"(addr));
}
__device__ __forceinline__ void cpasync16(uint32_t saddr, const void* gaddr) {
    asm volatile("cp.async.cg.shared.global [%0], [%1], 16;" :: "r"(saddr), "l"(gaddr));
}
__device__ __forceinline__ void cpasync_commit() { asm volatile("cp.async.commit_group;"); }
__device__ __forceinline__ void cpasync_wait0()  { asm volatile("cp.async.wait_group 0;"); }

__global__ void __launch_bounds__(128, 3)
fa_fwd_kernel(const float* __restrict__ qkv, float* __restrict__ out)
{
    extern __shared__ float smem[];
    const uint32_t smem_base = (uint32_t)__cvta_generic_to_shared(smem);

    const int tid  = threadIdx.x;
    const int warp = tid >> 5;
    const int lane = tid & 31;
    const int g    = lane >> 2;
    const int t    = lane & 3;

    const int mtile = blockIdx.x;
    const int b     = blockIdx.y / NH;
    const int h     = blockIdx.y % NH;
    const int m0    = mtile * BM;

    const int rowstr = 3 * NH * DH;          // 3072 floats per seq position
    const float* qbase = qkv + (size_t)b * SEQ * rowstr + h * DH;
    const float* kbase = qbase + NH * DH;    // V at +NH*DH more

    // ---- ldmatrix per-lane address components ----
    // S (B = K^T, non-trans): tiles {keys 16nfp+0..7 x dlo, same keys x dhi, keys+8 x dlo, +8 x dhi}
    const int krow_l = (lane & 7) | ((lane & 16) >> 1);   // 0..15 key-row within nf-pair
    const int kdh_l  = (lane >> 3) & 1;                   // d half (0/8)
    const uint32_t kfrag_base = smem_base + SM_KH + (uint32_t)(krow_l * H_STRIDE + kdh_l * 4) * 4u;
    // PV (B = V, trans): tiles {kv 16ks+0..7 x dlo8, kv+8 x dlo8, kv.. x dhi8, ..}
    const int vrow_l = lane & 15;                          // kv-row within ks block
    const int vdh_l  = lane >> 4;                          // d sub-half (0/8 f16 -> 0/4 words)
    const uint32_t vfrag_base = smem_base + SM_VH + (uint32_t)(vrow_l * H_STRIDE + vdh_l * 4) * 4u;

    // ---- cp.async coords: 8 float4 K + 8 float4 V per thread per tile ----
    uint32_t kdst[8], vdst[8];
    int grow[8], gcol[8];
#pragma unroll
    for (int i = 0; i < 8; i++) {
        int idx = tid + i * 128;
        int row = idx >> 4;
        int c4  = (idx & 15) << 2;
        grow[i] = row; gcol[i] = c4;
        kdst[i] = smem_base + SM_KSTG + (uint32_t)(row * KSTG_STRIDE + c4) * 4u;
        vdst[i] = smem_base + SM_VSTG + (uint32_t)(row * KSTG_STRIDE + c4) * 4u;
    }

    // issue tile 0 loads
#pragma unroll
    for (int i = 0; i < 8; i++) {
        const float* gk = kbase + (size_t)grow[i] * rowstr + gcol[i];
        cpasync16(kdst[i], gk);
        cpasync16(vdst[i], gk + NH * DH);
    }
    cpasync_commit();

    // ---- Q -> f16 A-fragments, scale folded (overlaps cp.async) ----
    const float qs = 0.125f * 1.4426950408889634f;
    uint32_t qa[4][4];
    {
        const float* q0 = qbase + (size_t)(m0 + warp * 16 + g) * rowstr;
        const float* q1 = q0 + (size_t)8 * rowstr;
#pragma unroll
        for (int ks = 0; ks < 4; ks++) {
            int c = ks * 16 + 2 * t;
            float2 a0 = *(const float2*)(q0 + c);
            float2 a1 = *(const float2*)(q1 + c);
            float2 a2 = *(const float2*)(q0 + c + 8);
            float2 a3 = *(const float2*)(q1 + c + 8);
            qa[ks][0] = packf16(a0.x * qs, a0.y * qs);
            qa[ks][1] = packf16(a1.x * qs, a1.y * qs);
            qa[ks][2] = packf16(a2.x * qs, a2.y * qs);
            qa[ks][3] = packf16(a3.x * qs, a3.y * qs);
        }
    }

    // conversion-pass assignment: one half-row per thread
    const int crow = tid & 63;          // row 0..63
    const int chalf = tid >> 6;         // which 32-element half

    float mr0 = -INFINITY, mr1 = -INFINITY;
    float l0 = 0.f, l1 = 0.f;
    float oacc[8][4];
#pragma unroll
    for (int nf = 0; nf < 8; nf++) {
        oacc[nf][0] = 0.f; oacc[nf][1] = 0.f; oacc[nf][2] = 0.f; oacc[nf][3] = 0.f;
    }

    for (int it = 0; it <= mtile; it++) {
        cpasync_wait0();
        __syncthreads();    // staging has tile it; f16 bufs free (prev compute done)

        // ---- fp32 staging -> f16 tiles (row-major both; V transposed later by ldmatrix.trans) ----
        {
            const float* ksrc = smem + crow * KSTG_STRIDE + chalf * 32;
            const float* vsrc = smem + 64 * KSTG_STRIDE + crow * KSTG_STRIDE + chalf * 32;
            uint32_t kh = smem_base + SM_KH + (uint32_t)(crow * H_STRIDE + chalf * 16) * 4u;
            uint32_t vh = smem_base + SM_VH + (uint32_t)(crow * H_STRIDE + chalf * 16) * 4u;
#pragma unroll
            for (int i = 0; i < 8; i++) {
                float4 kv4 = *(const float4*)(ksrc + i * 4);
                float4 vv4 = *(const float4*)(vsrc + i * 4);
                uint32_t kp0 = packf16(kv4.x, kv4.y), kp1 = packf16(kv4.z, kv4.w);
                uint32_t vp0 = packf16(vv4.x, vv4.y), vp1 = packf16(vv4.z, vv4.w);
                asm volatile("st.shared.v2.b32 [%0], {%1,%2};" :: "r"(kh + i * 8u), "r"(kp0), "r"(kp1));
                asm volatile("st.shared.v2.b32 [%0], {%1,%2};" :: "r"(vh + i * 8u), "r"(vp0), "r"(vp1));
            }
        }
        __syncthreads();    // f16 tiles ready; staging free

        // prefetch tile it+1 into staging (overlaps compute)
        if (it < mtile) {
            const size_t goff = (size_t)(it + 1) * BN * rowstr;
#pragma unroll
            for (int i = 0; i < 8; i++) {
                const float* gk = kbase + goff + (size_t)grow[i] * rowstr + gcol[i];
                cpasync16(kdst[i], gk);
                cpasync16(vdst[i], gk + NH * DH);
            }
            cpasync_commit();
        }

        // ---- S = (Q*scale) @ K^T ----
        float sacc[8][4];
#pragma unroll
        for (int nf = 0; nf < 8; nf++) {
            sacc[nf][0] = 0.f; sacc[nf][1] = 0.f; sacc[nf][2] = 0.f; sacc[nf][3] = 0.f;
        }
#pragma unroll
        for (int ks = 0; ks < 4; ks++) {
#pragma unroll
            for (int nfp = 0; nfp < 4; nfp++) {
                uint32_t bf[4];
                ldm_x4(bf, kfrag_base + (uint32_t)(nfp * 16 * H_STRIDE + ks * 8) * 4u);
                mma_f16(sacc[2 * nfp],     qa[ks], bf[0], bf[1]);
                mma_f16(sacc[2 * nfp + 1], qa[ks], bf[2], bf[3]);
            }
        }

        // ---- causal mask on diagonal tile ----
        if (it == mtile) {
            const int rl0 = warp * 16 + g;
            const int rl1 = rl0 + 8;
#pragma unroll
            for (int nf = 0; nf < 8; nf++) {
                int c0 = nf * 8 + 2 * t;
                int c1 = c0 + 1;
                if (c0 > rl0) sacc[nf][0] = -1e30f;
                if (c1 > rl0) sacc[nf][1] = -1e30f;
                if (c0 > rl1) sacc[nf][2] = -1e30f;
                if (c1 > rl1) sacc[nf][3] = -1e30f;
            }
        }

        // ---- online softmax (base-2 domain; scale already folded into Q) ----
        float rmax0 = -INFINITY, rmax1 = -INFINITY;
#pragma unroll
        for (int nf = 0; nf < 8; nf++) {
            rmax0 = fmaxf(rmax0, fmaxf(sacc[nf][0], sacc[nf][1]));
            rmax1 = fmaxf(rmax1, fmaxf(sacc[nf][2], sacc[nf][3]));
        }
        rmax0 = fmaxf(rmax0, __shfl_xor_sync(0xffffffffu, rmax0, 1));
        rmax0 = fmaxf(rmax0, __shfl_xor_sync(0xffffffffu, rmax0, 2));
        rmax1 = fmaxf(rmax1, __shfl_xor_sync(0xffffffffu, rmax1, 1));
        rmax1 = fmaxf(rmax1, __shfl_xor_sync(0xffffffffu, rmax1, 2));

        float mn0 = fmaxf(mr0, rmax0);
        float mn1 = fmaxf(mr1, rmax1);
        float alpha0 = ex2(mr0 - mn0);
        float alpha1 = ex2(mr1 - mn1);
        mr0 = mn0; mr1 = mn1;
        l0 *= alpha0; l1 *= alpha1;
#pragma unroll
        for (int nf = 0; nf < 8; nf++) {
            oacc[nf][0] *= alpha0; oacc[nf][1] *= alpha0;
            oacc[nf][2] *= alpha1; oacc[nf][3] *= alpha1;
        }

        // P = exp2(S - mn), packed f16x2 in-place as PV A-fragments (no shuffles needed)
        uint32_t pk0[8], pk1[8];
        float rs0 = 0.f, rs1 = 0.f;
#pragma unroll
        for (int nf = 0; nf < 8; nf++) {
            float p00 = ex2(sacc[nf][0] - mn0);
            float p01 = ex2(sacc[nf][1] - mn0);
            float p10 = ex2(sacc[nf][2] - mn1);
            float p11 = ex2(sacc[nf][3] - mn1);
            rs0 += p00 + p01;
            rs1 += p10 + p11;
            pk0[nf] = packf16(p00, p01);
            pk1[nf] = packf16(p10, p11);
        }
        rs0 += __shfl_xor_sync(0xffffffffu, rs0, 1);
        rs0 += __shfl_xor_sync(0xffffffffu, rs0, 2);
        rs1 += __shfl_xor_sync(0xffffffffu, rs1, 1);
        rs1 += __shfl_xor_sync(0xffffffffu, rs1, 2);
        l0 += rs0; l1 += rs1;

        // ---- O += P @ V  (V B-fragments via ldmatrix.trans on row-major V) ----
#pragma unroll
        for (int ks = 0; ks < 4; ks++) {
            uint32_t a[4] = { pk0[2 * ks], pk1[2 * ks], pk0[2 * ks + 1], pk1[2 * ks + 1] };
#pragma unroll
            for (int nfp = 0; nfp < 4; nfp++) {
                uint32_t bf[4];
                ldm_x4_t(bf, vfrag_base + (uint32_t)(ks * 16 * H_STRIDE + nfp * 8) * 4u);
                mma_f16(oacc[2 * nfp],     a, bf[0], bf[1]);
                mma_f16(oacc[2 * nfp + 1], a, bf[2], bf[3]);
            }
        }
    }

    // ---- epilogue ----
    const float inv0 = 1.0f / l0;
    const float inv1 = 1.0f / l1;
    const int r0 = m0 + warp * 16 + g;
    float* o0 = out + ((size_t)(b * SEQ + r0) * NH + h) * DH;
    float* o1 = o0 + (size_t)8 * NH * DH;
#pragma unroll
    for (int nf = 0; nf < 8; nf++) {
        int c = nf * 8 + 2 * t;
        *(float2*)(o0 + c) = make_float2(oacc[nf][0] * inv0, oacc[nf][1] * inv0);
        *(float2*)(o1 + c) = make_float2(oacc[nf][2] * inv1, oacc[nf][3] * inv1);
    }
}

extern "C" void kernel_launch(void* const* d_in, const int* in_sizes, int n_in,
                              void* d_out, int out_size)
{
    (void)in_sizes; (void)n_in; (void)out_size;
    const float* qkv = (const float*)d_in[0];
    float* out = (float*)d_out;

    cudaFuncSetAttribute(fa_fwd_kernel, cudaFuncAttributeMaxDynamicSharedMemorySize, SM_BYTES);

    dim3 grid(SEQ / BM, B_SZ * NH);
    fa_fwd_kernel<<<grid, 128, SM_BYTES>>>(qkv, out);
}

// round 10
// speedup vs baseline: 1.4955x; 1.0553x over previous
#include <cuda_runtime.h>
#include <cstdint>
#include <math.h>

// qkv [B, S, 3, H, D] fp32 -> out [B, S, H, D] fp32
#define B_SZ 2
#define SEQ  2048
#define NH   16
#define DH   64
#define BM   64
#define BN   64

// smem layout (bytes)
#define KSTG_STRIDE 68              // fp32 staging row stride (words)
#define H_STRIDE    36              // f16 tile row stride (32-bit words): 32 data + 4 pad
#define SM_KSTG 0
#define SM_VSTG (64*KSTG_STRIDE*4)               // 17408
#define SM_HBUF (2*64*KSTG_STRIDE*4)             // 34816: start of f16 double buffer
#define KH_BYTES (64*H_STRIDE*4)                 // 9216
#define HBUF_BYTES (2*KH_BYTES)                  // KH+VH per buffer = 18432
#define SM_KH0 SM_HBUF
#define SM_VH0 (SM_HBUF + KH_BYTES)
#define SM_BYTES (SM_HBUF + 2*HBUF_BYTES)        // 71680

__device__ __forceinline__ uint32_t packf16(float lo, float hi) {
    uint32_t r;
    asm("cvt.rn.f16x2.f32 %0, %1, %2;" : "=r"(r) : "f"(hi), "f"(lo));
    return r;
}
__device__ __forceinline__ float ex2(float x) {
    float r; asm("ex2.approx.ftz.f32 %0, %1;" : "=f"(r) : "f"(x)); return r;
}
__device__ __forceinline__ void mma_f16(float c[4], const uint32_t a[4],
                                        uint32_t b0, uint32_t b1) {
    asm volatile(
        "mma.sync.aligned.m16n8k16.row.col.f32.f16.f16.f32 "
        "{%0,%1,%2,%3}, {%4,%5,%6,%7}, {%8,%9}, {%0,%1,%2,%3};"
        : "+f"(c[0]), "+f"(c[1]), "+f"(c[2]), "+f"(c[3])
        : "r"(a[0]), "r"(a[1]), "r"(a[2]), "r"(a[3]), "r"(b0), "r"(b1));
}
__device__ __forceinline__ void ldm_x4(uint32_t b[4], uint32_t addr) {
    asm volatile("ldmatrix.sync.aligned.m8n8.x4.shared.b16 {%0,%1,%2,%3}, [%4];"
                 : "=r"(b[0]), "=r"(b[1]), "=r"(b[2]), "=r"(b[3]) : "r"(addr));
}
__device__ __forceinline__ void ldm_x4_t(uint32_t b[4], uint32_t addr) {
    asm volatile("ldmatrix.sync.aligned.m8n8.x4.trans.shared.b16 {%0,%1,%2,%3}, [%4];"
                 : "=r"(b[0]), "=r"(b[1]), "=r"(b[2]), "=r"(b[3]) : "r"(addr));
}
__device__ __forceinline__ void sts64(uint32_t addr, uint32_t w0, uint32_t w1) {
    asm volatile("st.shared.v2.b32 [%0], {%1,%2};" :: "r"(addr), "r"(w0), "r"(w1));
}
__device__ __forceinline__ void cpasync16(uint32_t saddr, const void* gaddr) {
    asm volatile("cp.async.cg.shared.global [%0], [%1], 16;" :: "r"(saddr), "l"(gaddr));
}
__device__ __forceinline__ void cpasync_commit() { asm volatile("cp.async.commit_group;"); }
__device__ __forceinline__ void cpasync_wait0()  { asm volatile("cp.async.wait_group 0;"); }

__global__ void __launch_bounds__(128, 3)
fa_fwd_kernel(const float* __restrict__ qkv, float* __restrict__ out)
{
    extern __shared__ float smem[];
    const uint32_t smem_base = (uint32_t)__cvta_generic_to_shared(smem);

    const int tid  = threadIdx.x;
    const int warp = tid >> 5;
    const int lane = tid & 31;
    const int g    = lane >> 2;
    const int t    = lane & 3;

    const int mtile = blockIdx.x;
    const int b     = blockIdx.y / NH;
    const int h     = blockIdx.y % NH;
    const int m0    = mtile * BM;

    const int rowstr = 3 * NH * DH;          // 3072 floats per seq position
    const float* qbase = qkv + (size_t)b * SEQ * rowstr + h * DH;
    const float* kbase = qbase + NH * DH;    // V at +NH*DH more

    // ---- ldmatrix per-lane address components (within f16 buffer 0) ----
    const int krow_l = (lane & 7) | ((lane & 16) >> 1);
    const int kdh_l  = (lane >> 3) & 1;
    const uint32_t kfrag0 = smem_base + SM_KH0 + (uint32_t)(krow_l * H_STRIDE + kdh_l * 4) * 4u;
    const int vrow_l = lane & 15;
    const int vdh_l  = lane >> 4;
    const uint32_t vfrag0 = smem_base + SM_VH0 + (uint32_t)(vrow_l * H_STRIDE + vdh_l * 4) * 4u;

    // ---- per-thread cp.async + conversion coords (each thread converts its OWN copies) ----
    uint32_t kdst[8], vdst[8];        // staging dst (smem addr)
    uint32_t hkof[8], hvof[8];        // f16 dst byte offsets within a buffer region
    const float *kstg[8], *vstg[8];   // staging src (generic ptr)
    int grow[8], gcol[8];
#pragma unroll
    for (int i = 0; i < 8; i++) {
        int idx = tid + i * 128;
        int row = idx >> 4;
        int c4  = (idx & 15) << 2;
        grow[i] = row; gcol[i] = c4;
        kdst[i] = smem_base + SM_KSTG + (uint32_t)(row * KSTG_STRIDE + c4) * 4u;
        vdst[i] = smem_base + SM_VSTG + (uint32_t)(row * KSTG_STRIDE + c4) * 4u;
        kstg[i] = smem + row * KSTG_STRIDE + c4;
        vstg[i] = smem + (SM_VSTG / 4) + row * KSTG_STRIDE + c4;
        hkof[i] = (uint32_t)(row * H_STRIDE + (c4 >> 1)) * 4u;
        hvof[i] = hkof[i];
    }

    // ---- issue tile 0 loads ----
#pragma unroll
    for (int i = 0; i < 8; i++) {
        const float* gk = kbase + (size_t)grow[i] * rowstr + gcol[i];
        cpasync16(kdst[i], gk);
        cpasync16(vdst[i], gk + NH * DH);
    }
    cpasync_commit();

    // ---- Q -> f16 A-fragments, scale folded (overlaps cp.async) ----
    const float qs = 0.125f * 1.4426950408889634f;
    uint32_t qa[4][4];
    {
        const float* q0 = qbase + (size_t)(m0 + warp * 16 + g) * rowstr;
        const float* q1 = q0 + (size_t)8 * rowstr;
#pragma unroll
        for (int ks = 0; ks < 4; ks++) {
            int c = ks * 16 + 2 * t;
            float2 a0 = *(const float2*)(q0 + c);
            float2 a1 = *(const float2*)(q1 + c);
            float2 a2 = *(const float2*)(q0 + c + 8);
            float2 a3 = *(const float2*)(q1 + c + 8);
            qa[ks][0] = packf16(a0.x * qs, a0.y * qs);
            qa[ks][1] = packf16(a1.x * qs, a1.y * qs);
            qa[ks][2] = packf16(a2.x * qs, a2.y * qs);
            qa[ks][3] = packf16(a3.x * qs, a3.y * qs);
        }
    }

    // ---- prologue: convert tile 0 (own data only -> just own wait needed) ----
    cpasync_wait0();
    {
        const uint32_t khd = smem_base + SM_KH0;   // buffer 0
        const uint32_t vhd = smem_base + SM_VH0;
#pragma unroll
        for (int i = 0; i < 8; i++) {
            float4 kv = *(const float4*)kstg[i];
            float4 vv = *(const float4*)vstg[i];
            sts64(khd + hkof[i], packf16(kv.x, kv.y), packf16(kv.z, kv.w));
            sts64(vhd + hvof[i], packf16(vv.x, vv.y), packf16(vv.z, vv.w));
        }
    }
    __syncthreads();    // f16 tile 0 visible to all
    if (mtile > 0) {
        const size_t goff = (size_t)BN * rowstr;
#pragma unroll
        for (int i = 0; i < 8; i++) {
            const float* gk = kbase + goff + (size_t)grow[i] * rowstr + gcol[i];
            cpasync16(kdst[i], gk);
            cpasync16(vdst[i], gk + NH * DH);
        }
        cpasync_commit();
    }

    float mr0 = -INFINITY, mr1 = -INFINITY;
    float l0 = 0.f, l1 = 0.f;
    float oacc[8][4];
#pragma unroll
    for (int nf = 0; nf < 8; nf++) {
        oacc[nf][0] = 0.f; oacc[nf][1] = 0.f; oacc[nf][2] = 0.f; oacc[nf][3] = 0.f;
    }

    for (int it = 0; it <= mtile; it++) {
        const uint32_t cur = (uint32_t)(it & 1);
        const uint32_t nb  = cur ^ 1u;
        const uint32_t kfb = kfrag0 + cur * HBUF_BYTES;
        const uint32_t vfb = vfrag0 + cur * HBUF_BYTES;
        const uint32_t khd = smem_base + SM_KH0 + nb * HBUF_BYTES;
        const uint32_t vhd = smem_base + SM_VH0 + nb * HBUF_BYTES;
        const bool conv = (it < mtile);

        if (conv) cpasync_wait0();   // own copies of tile it+1 arrived

        float sacc[8][4];
#pragma unroll
        for (int nf = 0; nf < 8; nf++) {
            sacc[nf][0] = 0.f; sacc[nf][1] = 0.f; sacc[nf][2] = 0.f; sacc[nf][3] = 0.f;
        }

        // ---- S-mma first half, with K-conversion chunk 0 pipelined under it ----
        float4 c0, c1, c2, c3;
        if (conv) { c0 = *(const float4*)kstg[0]; c1 = *(const float4*)kstg[1];
                    c2 = *(const float4*)kstg[2]; c3 = *(const float4*)kstg[3]; }
#pragma unroll
        for (int ks = 0; ks < 2; ks++) {
#pragma unroll
            for (int nfp = 0; nfp < 4; nfp++) {
                uint32_t bf[4];
                ldm_x4(bf, kfb + (uint32_t)(nfp * 16 * H_STRIDE + ks * 8) * 4u);
                mma_f16(sacc[2 * nfp],     qa[ks], bf[0], bf[1]);
                mma_f16(sacc[2 * nfp + 1], qa[ks], bf[2], bf[3]);
            }
        }
        if (conv) {
            sts64(khd + hkof[0], packf16(c0.x, c0.y), packf16(c0.z, c0.w));
            sts64(khd + hkof[1], packf16(c1.x, c1.y), packf16(c1.z, c1.w));
            sts64(khd + hkof[2], packf16(c2.x, c2.y), packf16(c2.z, c2.w));
            sts64(khd + hkof[3], packf16(c3.x, c3.y), packf16(c3.z, c3.w));
            c0 = *(const float4*)kstg[4]; c1 = *(const float4*)kstg[5];
            c2 = *(const float4*)kstg[6]; c3 = *(const float4*)kstg[7];
        }
#pragma unroll
        for (int ks = 2; ks < 4; ks++) {
#pragma unroll
            for (int nfp = 0; nfp < 4; nfp++) {
                uint32_t bf[4];
                ldm_x4(bf, kfb + (uint32_t)(nfp * 16 * H_STRIDE + ks * 8) * 4u);
                mma_f16(sacc[2 * nfp],     qa[ks], bf[0], bf[1]);
                mma_f16(sacc[2 * nfp + 1], qa[ks], bf[2], bf[3]);
            }
        }
        if (conv) {
            sts64(khd + hkof[4], packf16(c0.x, c0.y), packf16(c0.z, c0.w));
            sts64(khd + hkof[5], packf16(c1.x, c1.y), packf16(c1.z, c1.w));
            sts64(khd + hkof[6], packf16(c2.x, c2.y), packf16(c2.z, c2.w));
            sts64(khd + hkof[7], packf16(c3.x, c3.y), packf16(c3.z, c3.w));
        }

        // ---- causal mask on diagonal tile ----
        if (it == mtile) {
            const int rl0 = warp * 16 + g;
            const int rl1 = rl0 + 8;
#pragma unroll
            for (int nf = 0; nf < 8; nf++) {
                int cc0 = nf * 8 + 2 * t;
                int cc1 = cc0 + 1;
                if (cc0 > rl0) sacc[nf][0] = -1e30f;
                if (cc1 > rl0) sacc[nf][1] = -1e30f;
                if (cc0 > rl1) sacc[nf][2] = -1e30f;
                if (cc1 > rl1) sacc[nf][3] = -1e30f;
            }
        }

        // ---- online softmax (base-2 domain) ----
        float rmax0 = -INFINITY, rmax1 = -INFINITY;
#pragma unroll
        for (int nf = 0; nf < 8; nf++) {
            rmax0 = fmaxf(rmax0, fmaxf(sacc[nf][0], sacc[nf][1]));
            rmax1 = fmaxf(rmax1, fmaxf(sacc[nf][2], sacc[nf][3]));
        }
        rmax0 = fmaxf(rmax0, __shfl_xor_sync(0xffffffffu, rmax0, 1));
        rmax0 = fmaxf(rmax0, __shfl_xor_sync(0xffffffffu, rmax0, 2));
        rmax1 = fmaxf(rmax1, __shfl_xor_sync(0xffffffffu, rmax1, 1));
        rmax1 = fmaxf(rmax1, __shfl_xor_sync(0xffffffffu, rmax1, 2));

        float mn0 = fmaxf(mr0, rmax0);
        float mn1 = fmaxf(mr1, rmax1);
        float alpha0 = ex2(mr0 - mn0);
        float alpha1 = ex2(mr1 - mn1);
        mr0 = mn0; mr1 = mn1;
        l0 *= alpha0; l1 *= alpha1;
#pragma unroll
        for (int nf = 0; nf < 8; nf++) {
            oacc[nf][0] *= alpha0; oacc[nf][1] *= alpha0;
            oacc[nf][2] *= alpha1; oacc[nf][3] *= alpha1;
        }

        uint32_t pk0[8], pk1[8];
        float rs0 = 0.f, rs1 = 0.f;
#pragma unroll
        for (int nf = 0; nf < 8; nf++) {
            float p00 = ex2(sacc[nf][0] - mn0);
            float p01 = ex2(sacc[nf][1] - mn0);
            float p10 = ex2(sacc[nf][2] - mn1);
            float p11 = ex2(sacc[nf][3] - mn1);
            rs0 += p00 + p01;
            rs1 += p10 + p11;
            pk0[nf] = packf16(p00, p01);
            pk1[nf] = packf16(p10, p11);
        }
        rs0 += __shfl_xor_sync(0xffffffffu, rs0, 1);
        rs0 += __shfl_xor_sync(0xffffffffu, rs0, 2);
        rs1 += __shfl_xor_sync(0xffffffffu, rs1, 1);
        rs1 += __shfl_xor_sync(0xffffffffu, rs1, 2);
        l0 += rs0; l1 += rs1;

        // ---- PV-mma, with V-conversion pipelined under it ----
        if (conv) { c0 = *(const float4*)vstg[0]; c1 = *(const float4*)vstg[1];
                    c2 = *(const float4*)vstg[2]; c3 = *(const float4*)vstg[3]; }
#pragma unroll
        for (int ks = 0; ks < 2; ks++) {
            uint32_t a[4] = { pk0[2 * ks], pk1[2 * ks], pk0[2 * ks + 1], pk1[2 * ks + 1] };
#pragma unroll
            for (int nfp = 0; nfp < 4; nfp++) {
                uint32_t bf[4];
                ldm_x4_t(bf, vfb + (uint32_t)(ks * 16 * H_STRIDE + nfp * 8) * 4u);
                mma_f16(oacc[2 * nfp],     a, bf[0], bf[1]);
                mma_f16(oacc[2 * nfp + 1], a, bf[2], bf[3]);
            }
        }
        if (conv) {
            sts64(vhd + hvof[0], packf16(c0.x, c0.y), packf16(c0.z, c0.w));
            sts64(vhd + hvof[1], packf16(c1.x, c1.y), packf16(c1.z, c1.w));
            sts64(vhd + hvof[2], packf16(c2.x, c2.y), packf16(c2.z, c2.w));
            sts64(vhd + hvof[3], packf16(c3.x, c3.y), packf16(c3.z, c3.w));
            c0 = *(const float4*)vstg[4]; c1 = *(const float4*)vstg[5];
            c2 = *(const float4*)vstg[6]; c3 = *(const float4*)vstg[7];
        }
#pragma unroll
        for (int ks = 2; ks < 4; ks++) {
            uint32_t a[4] = { pk0[2 * ks], pk1[2 * ks], pk0[2 * ks + 1], pk1[2 * ks + 1] };
#pragma unroll
            for (int nfp = 0; nfp < 4; nfp++) {
                uint32_t bf[4];
                ldm_x4_t(bf, vfb + (uint32_t)(ks * 16 * H_STRIDE + nfp * 8) * 4u);
                mma_f16(oacc[2 * nfp],     a, bf[0], bf[1]);
                mma_f16(oacc[2 * nfp + 1], a, bf[2], bf[3]);
            }
        }
        if (conv) {
            sts64(vhd + hvof[4], packf16(c0.x, c0.y), packf16(c0.z, c0.w));
            sts64(vhd + hvof[5], packf16(c1.x, c1.y), packf16(c1.z, c1.w));
            sts64(vhd + hvof[6], packf16(c2.x, c2.y), packf16(c2.z, c2.w));
            sts64(vhd + hvof[7], packf16(c3.x, c3.y), packf16(c3.z, c3.w));
        }

        __syncthreads();   // f16[nb] complete+visible; all reads of f16[cur] and staging done

        // issue cp.async for tile it+2 into (now free) staging
        if (it + 1 < mtile) {
            const size_t goff = (size_t)(it + 2) * BN * rowstr;
#pragma unroll
            for (int i = 0; i < 8; i++) {
                const float* gk = kbase + goff + (size_t)grow[i] * rowstr + gcol[i];
                cpasync16(kdst[i], gk);
                cpasync16(vdst[i], gk + NH * DH);
            }
            cpasync_commit();
        }
    }

    // ---- epilogue ----
    const float inv0 = 1.0f / l0;
    const float inv1 = 1.0f / l1;
    const int r0 = m0 + warp * 16 + g;
    float* o0 = out + ((size_t)(b * SEQ + r0) * NH + h) * DH;
    float* o1 = o0 + (size_t)8 * NH * DH;
#pragma unroll
    for (int nf = 0; nf < 8; nf++) {
        int c = nf * 8 + 2 * t;
        *(float2*)(o0 + c) = make_float2(oacc[nf][0] * inv0, oacc[nf][1] * inv0);
        *(float2*)(o1 + c) = make_float2(oacc[nf][2] * inv1, oacc[nf][3] * inv1);
    }
}

extern "C" void kernel_launch(void* const* d_in, const int* in_sizes, int n_in,
                              void* d_out, int out_size)
{
    (void)in_sizes; (void)n_in; (void)out_size;
    const float* qkv = (const float*)d_in[0];
    float* out = (float*)d_out;

    cudaFuncSetAttribute(fa_fwd_kernel, cudaFuncAttributeMaxDynamicSharedMemorySize, SM_BYTES);

    dim3 grid(SEQ / BM, B_SZ * NH);
    fa_fwd_kernel<<<grid, 128, SM_BYTES>>>(qkv, out);
}